// round 3
// baseline (speedup 1.0000x reference)
#include <cuda_runtime.h>

#define NN 100000
#define NE 640000
#define NF 128
#define NC 16

// Scratch (allocation-free rule: __device__ globals)
__device__ float g_yl[NN * NC];   // x @ W_l^T
__device__ float g_yr[NN * NC];   // x @ W_r^T
__device__ float g_agg[NN * NC];  // segment-sum of yl over edges
__device__ float g_deg[NN];       // in-degree (float)

// ---------------------------------------------------------------------------
// K0: zero agg + deg
// ---------------------------------------------------------------------------
__global__ void k_zero() {
    int i = blockIdx.x * blockDim.x + threadIdx.x;
    if (i < NN * 4) reinterpret_cast<float4*>(g_agg)[i] = make_float4(0.f, 0.f, 0.f, 0.f);
    if (i < NN) g_deg[i] = 0.f;
}

// ---------------------------------------------------------------------------
// K1: fused dual projection  yl = x @ W_l^T, yr = x @ W_r^T
// One thread per node. Weights (32 rows x 128) in smem, broadcast reads.
// ---------------------------------------------------------------------------
__global__ __launch_bounds__(256) void k_proj(const float* __restrict__ x,
                                              const float* __restrict__ Wl,
                                              const float* __restrict__ Wr) {
    __shared__ float4 sW[32 * 32];  // [c][k4]: c<16 -> W_l rows, c>=16 -> W_r rows
    int tid = threadIdx.x;
    for (int j = tid; j < 32 * 32; j += 256) {
        int c = j >> 5;
        int k4 = j & 31;
        const float* wrow = (c < 16) ? (Wl + c * NF) : (Wr + (c - 16) * NF);
        sW[j] = reinterpret_cast<const float4*>(wrow)[k4];
    }
    __syncthreads();

    int i = blockIdx.x * 256 + tid;
    if (i >= NN) return;

    float acc[32];
#pragma unroll
    for (int c = 0; c < 32; c++) acc[c] = 0.f;

    const float4* xr = reinterpret_cast<const float4*>(x + (size_t)i * NF);
#pragma unroll 4
    for (int k4 = 0; k4 < 32; k4++) {
        float4 xv = xr[k4];
#pragma unroll
        for (int c = 0; c < 32; c++) {
            float4 wv = sW[c * 32 + k4];
            acc[c] = fmaf(xv.x, wv.x, acc[c]);
            acc[c] = fmaf(xv.y, wv.y, acc[c]);
            acc[c] = fmaf(xv.z, wv.z, acc[c]);
            acc[c] = fmaf(xv.w, wv.w, acc[c]);
        }
    }

    float4* yl4 = reinterpret_cast<float4*>(g_yl + (size_t)i * NC);
    float4* yr4 = reinterpret_cast<float4*>(g_yr + (size_t)i * NC);
#pragma unroll
    for (int q = 0; q < 4; q++) {
        yl4[q] = make_float4(acc[q * 4 + 0], acc[q * 4 + 1], acc[q * 4 + 2], acc[q * 4 + 3]);
        yr4[q] = make_float4(acc[16 + q * 4 + 0], acc[16 + q * 4 + 1],
                             acc[16 + q * 4 + 2], acc[16 + q * 4 + 3]);
    }
}

// ---------------------------------------------------------------------------
// K2: edge scatter. edge_index is INT32 (JAX x64 disabled downcasts int64).
// One thread per edge: gather yl[src] (64B, L2-resident), vectorized f32
// reduction-add into agg[dst], plus one degree atomic.
// ---------------------------------------------------------------------------
__global__ __launch_bounds__(256) void k_scatter(const int* __restrict__ ei) {
    int e = blockIdx.x * blockDim.x + threadIdx.x;
    if (e >= NE) return;
    unsigned src = (unsigned)ei[e];
    unsigned dst = (unsigned)ei[NE + e];
    if (src >= NN || dst >= NN) return;  // never taken with valid input; avoids faults

    const float4* ysrc = reinterpret_cast<const float4*>(g_yl + (size_t)src * NC);
    float* d = g_agg + (size_t)dst * NC;
#pragma unroll
    for (int q = 0; q < 4; q++) {
        float4 v = ysrc[q];
        asm volatile("red.global.add.v4.f32 [%0], {%1, %2, %3, %4};"
                     :: "l"(d + q * 4), "f"(v.x), "f"(v.y), "f"(v.z), "f"(v.w)
                     : "memory");
    }
    atomicAdd(&g_deg[dst], 1.0f);
}

// ---------------------------------------------------------------------------
// K3: epilogue  out = relu(agg / max(deg,1) + b + yr)
// ---------------------------------------------------------------------------
__global__ __launch_bounds__(256) void k_finish(const float* __restrict__ b,
                                                float* __restrict__ out) {
    int i = blockIdx.x * blockDim.x + threadIdx.x;
    if (i >= NN) return;
    float inv = 1.0f / fmaxf(g_deg[i], 1.0f);

    const float4* a4 = reinterpret_cast<const float4*>(g_agg + (size_t)i * NC);
    const float4* y4 = reinterpret_cast<const float4*>(g_yr + (size_t)i * NC);
    const float4* b4 = reinterpret_cast<const float4*>(b);
    float4* o4 = reinterpret_cast<float4*>(out + (size_t)i * NC);
#pragma unroll
    for (int q = 0; q < 4; q++) {
        float4 a = a4[q];
        float4 y = y4[q];
        float4 bb = b4[q];
        float4 o;
        o.x = fmaxf(fmaf(a.x, inv, bb.x + y.x), 0.f);
        o.y = fmaxf(fmaf(a.y, inv, bb.y + y.y), 0.f);
        o.z = fmaxf(fmaf(a.z, inv, bb.z + y.z), 0.f);
        o.w = fmaxf(fmaf(a.w, inv, bb.w + y.w), 0.f);
        o4[q] = o;
    }
}

// ---------------------------------------------------------------------------
// Inputs (metadata order): x [N*F] f32, edge_index [2*E] i32,
//                          W_l [C*F] f32, b_l [C] f32, W_r [C*F] f32
// Output: [N*C] f32
// ---------------------------------------------------------------------------
extern "C" void kernel_launch(void* const* d_in, const int* in_sizes, int n_in,
                              void* d_out, int out_size) {
    const float* x = (const float*)d_in[0];
    const int* ei = (const int*)d_in[1];
    const float* Wl = (const float*)d_in[2];
    const float* bl = (const float*)d_in[3];
    const float* Wr = (const float*)d_in[4];
    float* out = (float*)d_out;

    k_zero<<<(NN * 4 + 255) / 256, 256>>>();
    k_proj<<<(NN + 255) / 256, 256>>>(x, Wl, Wr);
    k_scatter<<<(NE + 255) / 256, 256>>>(ei);
    k_finish<<<(NN + 255) / 256, 256>>>(bl, out);
}

// round 4
// speedup vs baseline: 1.0008x; 1.0008x over previous
#include <cuda_runtime.h>

#define NN 100000
#define NE 640000
#define NF 128
#define NC 16

// Scratch (allocation-free rule: __device__ globals)
__device__ float g_yl[NN * NC];   // x @ W_l^T
__device__ float g_yr[NN * NC];   // x @ W_r^T
__device__ float g_agg[NN * NC];  // segment-sum of yl over edges
__device__ float g_deg[NN];       // in-degree (float)

// ---------------------------------------------------------------------------
// K0: zero agg + deg
// ---------------------------------------------------------------------------
__global__ void k_zero() {
    int i = blockIdx.x * blockDim.x + threadIdx.x;
    if (i < NN * 4) reinterpret_cast<float4*>(g_agg)[i] = make_float4(0.f, 0.f, 0.f, 0.f);
    if (i < NN) g_deg[i] = 0.f;
}

// ---------------------------------------------------------------------------
// K1: fused dual projection  yl = x @ W_l^T, yr = x @ W_r^T
// One thread per node. Weights (32 rows x 128) in smem, broadcast reads.
// ---------------------------------------------------------------------------
__global__ __launch_bounds__(256) void k_proj(const float* __restrict__ x,
                                              const float* __restrict__ Wl,
                                              const float* __restrict__ Wr) {
    __shared__ float4 sW[32 * 32];  // [c][k4]: c<16 -> W_l rows, c>=16 -> W_r rows
    int tid = threadIdx.x;
    for (int j = tid; j < 32 * 32; j += 256) {
        int c = j >> 5;
        int k4 = j & 31;
        const float* wrow = (c < 16) ? (Wl + c * NF) : (Wr + (c - 16) * NF);
        sW[j] = reinterpret_cast<const float4*>(wrow)[k4];
    }
    __syncthreads();

    int i = blockIdx.x * 256 + tid;
    if (i >= NN) return;

    float acc[32];
#pragma unroll
    for (int c = 0; c < 32; c++) acc[c] = 0.f;

    const float4* xr = reinterpret_cast<const float4*>(x + (size_t)i * NF);
#pragma unroll 4
    for (int k4 = 0; k4 < 32; k4++) {
        float4 xv = xr[k4];
#pragma unroll
        for (int c = 0; c < 32; c++) {
            float4 wv = sW[c * 32 + k4];
            acc[c] = fmaf(xv.x, wv.x, acc[c]);
            acc[c] = fmaf(xv.y, wv.y, acc[c]);
            acc[c] = fmaf(xv.z, wv.z, acc[c]);
            acc[c] = fmaf(xv.w, wv.w, acc[c]);
        }
    }

    float4* yl4 = reinterpret_cast<float4*>(g_yl + (size_t)i * NC);
    float4* yr4 = reinterpret_cast<float4*>(g_yr + (size_t)i * NC);
#pragma unroll
    for (int q = 0; q < 4; q++) {
        yl4[q] = make_float4(acc[q * 4 + 0], acc[q * 4 + 1], acc[q * 4 + 2], acc[q * 4 + 3]);
        yr4[q] = make_float4(acc[16 + q * 4 + 0], acc[16 + q * 4 + 1],
                             acc[16 + q * 4 + 2], acc[16 + q * 4 + 3]);
    }
}

// ---------------------------------------------------------------------------
// K2: edge scatter. edge_index is INT32 (JAX x64 disabled downcasts int64).
// One thread per edge: gather yl[src] (64B, L2-resident), vectorized f32
// reduction-add into agg[dst], plus one degree atomic.
// ---------------------------------------------------------------------------
__global__ __launch_bounds__(256) void k_scatter(const int* __restrict__ ei) {
    int e = blockIdx.x * blockDim.x + threadIdx.x;
    if (e >= NE) return;
    unsigned src = (unsigned)ei[e];
    unsigned dst = (unsigned)ei[NE + e];
    if (src >= NN || dst >= NN) return;  // never taken with valid input; avoids faults

    const float4* ysrc = reinterpret_cast<const float4*>(g_yl + (size_t)src * NC);
    float* d = g_agg + (size_t)dst * NC;
#pragma unroll
    for (int q = 0; q < 4; q++) {
        float4 v = ysrc[q];
        asm volatile("red.global.add.v4.f32 [%0], {%1, %2, %3, %4};"
                     :: "l"(d + q * 4), "f"(v.x), "f"(v.y), "f"(v.z), "f"(v.w)
                     : "memory");
    }
    atomicAdd(&g_deg[dst], 1.0f);
}

// ---------------------------------------------------------------------------
// K3: epilogue  out = relu(agg / max(deg,1) + b + yr)
// ---------------------------------------------------------------------------
__global__ __launch_bounds__(256) void k_finish(const float* __restrict__ b,
                                                float* __restrict__ out) {
    int i = blockIdx.x * blockDim.x + threadIdx.x;
    if (i >= NN) return;
    float inv = 1.0f / fmaxf(g_deg[i], 1.0f);

    const float4* a4 = reinterpret_cast<const float4*>(g_agg + (size_t)i * NC);
    const float4* y4 = reinterpret_cast<const float4*>(g_yr + (size_t)i * NC);
    const float4* b4 = reinterpret_cast<const float4*>(b);
    float4* o4 = reinterpret_cast<float4*>(out + (size_t)i * NC);
#pragma unroll
    for (int q = 0; q < 4; q++) {
        float4 a = a4[q];
        float4 y = y4[q];
        float4 bb = b4[q];
        float4 o;
        o.x = fmaxf(fmaf(a.x, inv, bb.x + y.x), 0.f);
        o.y = fmaxf(fmaf(a.y, inv, bb.y + y.y), 0.f);
        o.z = fmaxf(fmaf(a.z, inv, bb.z + y.z), 0.f);
        o.w = fmaxf(fmaf(a.w, inv, bb.w + y.w), 0.f);
        o4[q] = o;
    }
}

// ---------------------------------------------------------------------------
// Inputs (metadata order): x [N*F] f32, edge_index [2*E] i32,
//                          W_l [C*F] f32, b_l [C] f32, W_r [C*F] f32
// Output: [N*C] f32
// ---------------------------------------------------------------------------
extern "C" void kernel_launch(void* const* d_in, const int* in_sizes, int n_in,
                              void* d_out, int out_size) {
    const float* x = (const float*)d_in[0];
    const int* ei = (const int*)d_in[1];
    const float* Wl = (const float*)d_in[2];
    const float* bl = (const float*)d_in[3];
    const float* Wr = (const float*)d_in[4];
    float* out = (float*)d_out;

    k_zero<<<(NN * 4 + 255) / 256, 256>>>();
    k_proj<<<(NN + 255) / 256, 256>>>(x, Wl, Wr);
    k_scatter<<<(NE + 255) / 256, 256>>>(ei);
    k_finish<<<(NN + 255) / 256, 256>>>(bl, out);
}

// round 7
// speedup vs baseline: 1.1786x; 1.1776x over previous
#include <cuda_runtime.h>

#define NN 100000
#define NE 640000
#define NF 128
#define NC 16

typedef unsigned long long u64;

// Scratch (allocation-free rule: __device__ globals)
__device__ float g_yl[NN * NC];   // x @ W_l^T
__device__ float g_yr[NN * NC];   // x @ W_r^T
__device__ float g_agg[NN * NC];  // segment-sum of yl over edges
__device__ float g_deg[NN];       // in-degree (float)

__device__ __forceinline__ u64 fma2(u64 a, u64 b, u64 c) {
    u64 d;
    asm("fma.rn.f32x2 %0, %1, %2, %3;" : "=l"(d) : "l"(a), "l"(b), "l"(c));
    return d;
}
__device__ __forceinline__ u64 bcast2(float x) {
    u64 d;
    asm("mov.b64 %0, {%1, %1};" : "=l"(d) : "f"(x));
    return d;
}
__device__ __forceinline__ u64 pack2(float lo, float hi) {
    u64 d;
    asm("mov.b64 %0, {%1, %2};" : "=l"(d) : "f"(lo), "f"(hi));
    return d;
}
__device__ __forceinline__ void unpack2(u64 d, float& lo, float& hi) {
    asm("mov.b64 {%0, %1}, %2;" : "=f"(lo), "=f"(hi) : "l"(d));
}

// ---------------------------------------------------------------------------
// K0: zero agg + deg
// ---------------------------------------------------------------------------
__global__ void k_zero() {
    int i = blockIdx.x * blockDim.x + threadIdx.x;
    if (i < NN * 4) reinterpret_cast<float4*>(g_agg)[i] = make_float4(0.f, 0.f, 0.f, 0.f);
    if (i < NN) g_deg[i] = 0.f;
}

// ---------------------------------------------------------------------------
// K1: fused dual projection with packed f32x2 FMA.
// sW2[p][k] holds the pair (W[2p][k], W[2p+1][k]); p<8 -> W_l, p>=8 -> W_r.
// Per k-pair: 16x LDS.128 (two k-steps of one channel pair), 2 broadcast
// packs, 32 fma.f32x2  ->  ~2x fewer fma-pipe instructions than scalar.
// ---------------------------------------------------------------------------
__global__ __launch_bounds__(256) void k_proj(const float* __restrict__ x,
                                              const float* __restrict__ Wl,
                                              const float* __restrict__ Wr) {
    __shared__ __align__(16) u64 sW2[16 * NF];  // 16 KB, [p][k]
    int tid = threadIdx.x;
    for (int j = tid; j < 16 * NF; j += 256) {
        int p = j >> 7;
        int k = j & 127;
        const float* r0;
        const float* r1;
        if (p < 8) {
            r0 = Wl + (2 * p) * NF;
            r1 = Wl + (2 * p + 1) * NF;
        } else {
            r0 = Wr + (2 * (p - 8)) * NF;
            r1 = Wr + (2 * (p - 8) + 1) * NF;
        }
        sW2[j] = pack2(r0[k], r1[k]);
    }
    __syncthreads();

    int i = blockIdx.x * 256 + tid;
    if (i >= NN) return;

    u64 acc[16];
#pragma unroll
    for (int p = 0; p < 16; p++) acc[p] = 0ull;

    const float4* xr = reinterpret_cast<const float4*>(x + (size_t)i * NF);
#pragma unroll 2
    for (int k4 = 0; k4 < 32; k4++) {
        float4 xv = xr[k4];
#pragma unroll
        for (int h = 0; h < 2; h++) {
            int k = k4 * 4 + h * 2;
            u64 xa = bcast2(h == 0 ? xv.x : xv.z);
            u64 xb = bcast2(h == 0 ? xv.y : xv.w);
#pragma unroll
            for (int p = 0; p < 16; p++) {
                ulonglong2 w = *reinterpret_cast<const ulonglong2*>(&sW2[p * NF + k]);
                acc[p] = fma2(xa, w.x, acc[p]);
                acc[p] = fma2(xb, w.y, acc[p]);
            }
        }
    }

    float v[32];
#pragma unroll
    for (int p = 0; p < 16; p++) unpack2(acc[p], v[2 * p], v[2 * p + 1]);

    float4* yl4 = reinterpret_cast<float4*>(g_yl + (size_t)i * NC);
    float4* yr4 = reinterpret_cast<float4*>(g_yr + (size_t)i * NC);
#pragma unroll
    for (int q = 0; q < 4; q++) {
        yl4[q] = make_float4(v[q * 4 + 0], v[q * 4 + 1], v[q * 4 + 2], v[q * 4 + 3]);
        yr4[q] = make_float4(v[16 + q * 4 + 0], v[16 + q * 4 + 1],
                             v[16 + q * 4 + 2], v[16 + q * 4 + 3]);
    }
}

// ---------------------------------------------------------------------------
// K2: edge scatter, 4 threads per edge (thread = edge x quarter-row).
// Each thread: 1 LDG.128 gather + 1 red.global.add.v4.f32; q==0 adds degree.
// 2.56M threads -> deep MLP to hide L2 gather/atomic latency.
// ---------------------------------------------------------------------------
__global__ __launch_bounds__(256) void k_scatter(const int* __restrict__ ei) {
    int t = blockIdx.x * blockDim.x + threadIdx.x;
    if (t >= NE * 4) return;
    int e = t >> 2;
    int q = t & 3;
    unsigned src = (unsigned)ei[e];
    unsigned dst = (unsigned)ei[NE + e];
    if (src >= NN || dst >= NN) return;  // never taken with valid input

    float4 v = reinterpret_cast<const float4*>(g_yl)[(size_t)src * 4 + q];
    float* d = g_agg + (size_t)dst * NC + q * 4;
    asm volatile("red.global.add.v4.f32 [%0], {%1, %2, %3, %4};"
                 :: "l"(d), "f"(v.x), "f"(v.y), "f"(v.z), "f"(v.w)
                 : "memory");
    if (q == 0) atomicAdd(&g_deg[dst], 1.0f);
}

// ---------------------------------------------------------------------------
// K3: epilogue, 4 threads per node: out = relu(agg/max(deg,1) + b + yr)
// ---------------------------------------------------------------------------
__global__ __launch_bounds__(256) void k_finish(const float* __restrict__ b,
                                                float* __restrict__ out) {
    int t = blockIdx.x * blockDim.x + threadIdx.x;
    if (t >= NN * 4) return;
    int i = t >> 2;
    int q = t & 3;
    float inv = 1.0f / fmaxf(g_deg[i], 1.0f);

    float4 a = reinterpret_cast<const float4*>(g_agg)[(size_t)i * 4 + q];
    float4 y = reinterpret_cast<const float4*>(g_yr)[(size_t)i * 4 + q];
    float4 bb = reinterpret_cast<const float4*>(b)[q];
    float4 o;
    o.x = fmaxf(fmaf(a.x, inv, bb.x + y.x), 0.f);
    o.y = fmaxf(fmaf(a.y, inv, bb.y + y.y), 0.f);
    o.z = fmaxf(fmaf(a.z, inv, bb.z + y.z), 0.f);
    o.w = fmaxf(fmaf(a.w, inv, bb.w + y.w), 0.f);
    reinterpret_cast<float4*>(out)[(size_t)i * 4 + q] = o;
}

// ---------------------------------------------------------------------------
// Inputs (metadata order): x [N*F] f32, edge_index [2*E] i32,
//                          W_l [C*F] f32, b_l [C] f32, W_r [C*F] f32
// Output: [N*C] f32
// ---------------------------------------------------------------------------
extern "C" void kernel_launch(void* const* d_in, const int* in_sizes, int n_in,
                              void* d_out, int out_size) {
    const float* x = (const float*)d_in[0];
    const int* ei = (const int*)d_in[1];
    const float* Wl = (const float*)d_in[2];
    const float* bl = (const float*)d_in[3];
    const float* Wr = (const float*)d_in[4];
    float* out = (float*)d_out;

    k_zero<<<(NN * 4 + 255) / 256, 256>>>();
    k_proj<<<(NN + 255) / 256, 256>>>(x, Wl, Wr);
    k_scatter<<<(NE * 4 + 255) / 256, 256>>>(ei);
    k_finish<<<(NN * 4 + 255) / 256, 256>>>(bl, out);
}

// round 9
// speedup vs baseline: 1.2378x; 1.0503x over previous
#include <cuda_runtime.h>

#define NN 100000
#define NE 640000
#define NF 128
#define NC 16

typedef unsigned long long u64;

// Scratch (allocation-free rule: __device__ globals)
__device__ float g_yl[NN * NC];   // x @ W_l^T
__device__ float g_yr[NN * NC];   // x @ W_r^T
__device__ float g_agg[NN * NC];  // segment-sum of yl over edges
__device__ float g_deg[NN];       // in-degree (float)

__device__ __forceinline__ u64 fma2(u64 a, u64 b, u64 c) {
    u64 d;
    asm("fma.rn.f32x2 %0, %1, %2, %3;" : "=l"(d) : "l"(a), "l"(b), "l"(c));
    return d;
}
__device__ __forceinline__ u64 bcast2(float x) {
    u64 d;
    asm("mov.b64 %0, {%1, %1};" : "=l"(d) : "f"(x));
    return d;
}
__device__ __forceinline__ u64 pack2(float lo, float hi) {
    u64 d;
    asm("mov.b64 %0, {%1, %2};" : "=l"(d) : "f"(lo), "f"(hi));
    return d;
}
__device__ __forceinline__ void unpack2(u64 d, float& lo, float& hi) {
    asm("mov.b64 {%0, %1}, %2;" : "=f"(lo), "=f"(hi) : "l"(d));
}

// ---------------------------------------------------------------------------
// K1: fused dual projection, 2 nodes/thread, packed f32x2 FMA.
// Also zero-initializes g_agg rows and g_deg for its nodes (replaces k_zero;
// k_scatter is ordered after this kernel, so the zeros are visible).
// sW2[p][k] holds (W[2p][k], W[2p+1][k]); p<8 -> W_l, p>=8 -> W_r.
// Each smem weight LDS.128 feeds 4 fma2 (2 nodes x 2 k-steps).
// ---------------------------------------------------------------------------
__global__ __launch_bounds__(256) void k_proj(const float* __restrict__ x,
                                              const float* __restrict__ Wl,
                                              const float* __restrict__ Wr) {
    __shared__ __align__(16) u64 sW2[16 * NF];  // 16 KB, [p][k]
    int tid = threadIdx.x;
    for (int j = tid; j < 16 * NF; j += 256) {
        int p = j >> 7;
        int k = j & 127;
        const float* r0;
        const float* r1;
        if (p < 8) {
            r0 = Wl + (2 * p) * NF;
            r1 = Wl + (2 * p + 1) * NF;
        } else {
            r0 = Wr + (2 * (p - 8)) * NF;
            r1 = Wr + (2 * (p - 8) + 1) * NF;
        }
        sW2[j] = pack2(r0[k], r1[k]);
    }
    __syncthreads();

    int base = blockIdx.x * 512;
    int i0 = base + tid;
    int i1 = base + 256 + tid;
    bool v0 = i0 < NN;
    bool v1 = i1 < NN;
    if (!v0) return;  // i1 > i0, so also invalid

    const float4 z4 = make_float4(0.f, 0.f, 0.f, 0.f);
    // zero-init agg + deg for our nodes (replaces k_zero)
    {
        float4* a0 = reinterpret_cast<float4*>(g_agg + (size_t)i0 * NC);
#pragma unroll
        for (int q = 0; q < 4; q++) a0[q] = z4;
        g_deg[i0] = 0.f;
        if (v1) {
            float4* a1 = reinterpret_cast<float4*>(g_agg + (size_t)i1 * NC);
#pragma unroll
            for (int q = 0; q < 4; q++) a1[q] = z4;
            g_deg[i1] = 0.f;
        }
    }

    u64 acc0[16], acc1[16];
#pragma unroll
    for (int p = 0; p < 16; p++) { acc0[p] = 0ull; acc1[p] = 0ull; }

    const float4* xr0 = reinterpret_cast<const float4*>(x + (size_t)i0 * NF);
    const float4* xr1 = reinterpret_cast<const float4*>(x + (size_t)(v1 ? i1 : i0) * NF);

#pragma unroll 2
    for (int k4 = 0; k4 < 32; k4++) {
        float4 xv0 = xr0[k4];
        float4 xv1 = xr1[k4];
#pragma unroll
        for (int h = 0; h < 2; h++) {
            int k = k4 * 4 + h * 2;
            u64 xa0 = bcast2(h == 0 ? xv0.x : xv0.z);
            u64 xb0 = bcast2(h == 0 ? xv0.y : xv0.w);
            u64 xa1 = bcast2(h == 0 ? xv1.x : xv1.z);
            u64 xb1 = bcast2(h == 0 ? xv1.y : xv1.w);
#pragma unroll
            for (int p = 0; p < 16; p++) {
                ulonglong2 w = *reinterpret_cast<const ulonglong2*>(&sW2[p * NF + k]);
                acc0[p] = fma2(xa0, w.x, acc0[p]);
                acc0[p] = fma2(xb0, w.y, acc0[p]);
                acc1[p] = fma2(xa1, w.x, acc1[p]);
                acc1[p] = fma2(xb1, w.y, acc1[p]);
            }
        }
    }

    float va[32];
#pragma unroll
    for (int p = 0; p < 16; p++) unpack2(acc0[p], va[2 * p], va[2 * p + 1]);
    float4* yl4 = reinterpret_cast<float4*>(g_yl + (size_t)i0 * NC);
    float4* yr4 = reinterpret_cast<float4*>(g_yr + (size_t)i0 * NC);
#pragma unroll
    for (int q = 0; q < 4; q++) {
        yl4[q] = make_float4(va[q * 4 + 0], va[q * 4 + 1], va[q * 4 + 2], va[q * 4 + 3]);
        yr4[q] = make_float4(va[16 + q * 4 + 0], va[16 + q * 4 + 1],
                             va[16 + q * 4 + 2], va[16 + q * 4 + 3]);
    }
    if (v1) {
#pragma unroll
        for (int p = 0; p < 16; p++) unpack2(acc1[p], va[2 * p], va[2 * p + 1]);
        float4* yl41 = reinterpret_cast<float4*>(g_yl + (size_t)i1 * NC);
        float4* yr41 = reinterpret_cast<float4*>(g_yr + (size_t)i1 * NC);
#pragma unroll
        for (int q = 0; q < 4; q++) {
            yl41[q] = make_float4(va[q * 4 + 0], va[q * 4 + 1], va[q * 4 + 2], va[q * 4 + 3]);
            yr41[q] = make_float4(va[16 + q * 4 + 0], va[16 + q * 4 + 1],
                                  va[16 + q * 4 + 2], va[16 + q * 4 + 3]);
        }
    }
}

// ---------------------------------------------------------------------------
// K2: edge scatter, 4 threads per edge (thread = edge x quarter-row).
// Each thread: 1 LDG.128 gather + 1 red.global.add.v4.f32; q==0 adds degree.
// ---------------------------------------------------------------------------
__global__ __launch_bounds__(256) void k_scatter(const int* __restrict__ ei) {
    int t = blockIdx.x * blockDim.x + threadIdx.x;
    if (t >= NE * 4) return;
    int e = t >> 2;
    int q = t & 3;
    unsigned src = (unsigned)ei[e];
    unsigned dst = (unsigned)ei[NE + e];
    if (src >= NN || dst >= NN) return;  // never taken with valid input

    float4 v = reinterpret_cast<const float4*>(g_yl)[(size_t)src * 4 + q];
    float* d = g_agg + (size_t)dst * NC + q * 4;
    asm volatile("red.global.add.v4.f32 [%0], {%1, %2, %3, %4};"
                 :: "l"(d), "f"(v.x), "f"(v.y), "f"(v.z), "f"(v.w)
                 : "memory");
    if (q == 0) atomicAdd(&g_deg[dst], 1.0f);
}

// ---------------------------------------------------------------------------
// K3: epilogue, 4 threads per node: out = relu(agg/max(deg,1) + b + yr)
// ---------------------------------------------------------------------------
__global__ __launch_bounds__(256) void k_finish(const float* __restrict__ b,
                                                float* __restrict__ out) {
    int t = blockIdx.x * blockDim.x + threadIdx.x;
    if (t >= NN * 4) return;
    int i = t >> 2;
    int q = t & 3;
    float inv = 1.0f / fmaxf(g_deg[i], 1.0f);

    float4 a = reinterpret_cast<const float4*>(g_agg)[(size_t)i * 4 + q];
    float4 y = reinterpret_cast<const float4*>(g_yr)[(size_t)i * 4 + q];
    float4 bb = reinterpret_cast<const float4*>(b)[q];
    float4 o;
    o.x = fmaxf(fmaf(a.x, inv, bb.x + y.x), 0.f);
    o.y = fmaxf(fmaf(a.y, inv, bb.y + y.y), 0.f);
    o.z = fmaxf(fmaf(a.z, inv, bb.z + y.z), 0.f);
    o.w = fmaxf(fmaf(a.w, inv, bb.w + y.w), 0.f);
    reinterpret_cast<float4*>(out)[(size_t)i * 4 + q] = o;
}

// ---------------------------------------------------------------------------
// Inputs (metadata order): x [N*F] f32, edge_index [2*E] i32,
//                          W_l [C*F] f32, b_l [C] f32, W_r [C*F] f32
// Output: [N*C] f32
// ---------------------------------------------------------------------------
extern "C" void kernel_launch(void* const* d_in, const int* in_sizes, int n_in,
                              void* d_out, int out_size) {
    const float* x = (const float*)d_in[0];
    const int* ei = (const int*)d_in[1];
    const float* Wl = (const float*)d_in[2];
    const float* bl = (const float*)d_in[3];
    const float* Wr = (const float*)d_in[4];
    float* out = (float*)d_out;

    k_proj<<<(NN + 511) / 512, 256>>>(x, Wl, Wr);
    k_scatter<<<(NE * 4 + 255) / 256, 256>>>(ei);
    k_finish<<<(NN * 4 + 255) / 256, 256>>>(bl, out);
}